// round 5
// baseline (speedup 1.0000x reference)
#include <cuda_runtime.h>
#include <cuda_bf16.h>
#include <cstdint>

#define D      128
#define NQ     512
#define NREF   100000
#define KNN    10
#define NSPLIT 36
#define NCH    22            // 36*22*128 = 101376 >= 100000
#define BN     128
#define ROWB   272           // smem tile row stride in bytes (136 bf16, 17x16B)
#define TILEB  (128 * ROWB)  // 34816 B per bf16 tile
#define SDS    129           // dist buffer row stride (floats)
#define SDF    (128 * SDS)
#define SMEM_BYTES (3 * TILEB + (SDF + 128 * KNN) * 4)

#define BIGF 3.0e37f

// ---------------------------------------------------------------- scratch
__device__ float g_x2[NQ];
__device__ float g_y2[NREF];
__device__ float g_cand[NSPLIT * KNN * NQ];
__device__ __nv_bfloat16 g_feat_bf[NQ * D];
__device__ __nv_bfloat16 g_refs_bf[NREF * D];

// ---------------------------------------------------------------- helpers
__device__ __forceinline__ uint32_t smem_u32(const void* p) {
    uint32_t a;
    asm("{ .reg .u64 t; cvta.to.shared.u64 t, %1; cvt.u32.u64 %0, t; }" : "=r"(a) : "l"(p));
    return a;
}
__device__ __forceinline__ void cpa16(uint32_t dst, const void* src, int bytes) {
    asm volatile("cp.async.cg.shared.global [%0], [%1], 16, %2;"
                 :: "r"(dst), "l"(src), "r"(bytes) : "memory");
}
#define CPA_COMMIT() asm volatile("cp.async.commit_group;" ::: "memory")
#define CPA_WAIT0()  asm volatile("cp.async.wait_group 0;" ::: "memory")

#define LDSM4(r, a)                                                            \
    asm volatile("ldmatrix.sync.aligned.m8n8.x4.shared.b16 {%0,%1,%2,%3}, [%4];" \
                 : "=r"((r)[0]), "=r"((r)[1]), "=r"((r)[2]), "=r"((r)[3])      \
                 : "r"(a))

__device__ __forceinline__ void mma_bf16(float* c, const uint32_t* a,
                                         uint32_t b0, uint32_t b1) {
    asm volatile("mma.sync.aligned.m16n8k16.row.col.f32.bf16.bf16.f32 "
                 "{%0,%1,%2,%3}, {%4,%5,%6,%7}, {%8,%9}, {%0,%1,%2,%3};"
                 : "+f"(c[0]), "+f"(c[1]), "+f"(c[2]), "+f"(c[3])
                 : "r"(a[0]), "r"(a[1]), "r"(a[2]), "r"(a[3]), "r"(b0), "r"(b1));
}

__device__ __forceinline__ void topk_insert(float (&tk)[KNN], float v) {
    if (v < tk[KNN - 1]) {
        tk[KNN - 1] = v;
        #pragma unroll
        for (int j = KNN - 1; j > 0; --j) {
            float lo = fminf(tk[j - 1], tk[j]);
            float hi = fmaxf(tk[j - 1], tk[j]);
            tk[j - 1] = lo;
            tk[j]     = hi;
        }
    }
}

// Load a 128-row x 128-col bf16 tile into smem [row][k], row stride ROWB bytes.
__device__ __forceinline__ void load_tile_bf(uint32_t dst, const __nv_bfloat16* __restrict__ src,
                                             int gbase, int glimit) {
    const int t = threadIdx.x;
    const int c = t & 15;           // 16B chunk along k (0..15)
    const int rb = t >> 4;          // row base (0..15)
    #pragma unroll
    for (int i = 0; i < 8; ++i) {
        const int row = rb + i * 16;
        const int gr = gbase + row;
        const int ok = (gr < glimit) ? 16 : 0;
        const int gc = (gr < glimit) ? gr : (glimit - 1);
        const __nv_bfloat16* s = src + (size_t)gc * D + c * 8;
        cpa16(dst + (uint32_t)(row * ROWB + c * 16), s, ok);
    }
}

// ---------------------------------------------------------------- kernel 1: norms + bf16 convert
__global__ void __launch_bounds__(256)
norms_kernel(const float* __restrict__ feat, const float* __restrict__ refs) {
    const int w = threadIdx.x >> 5, l = threadIdx.x & 31;
    const int base_row = (blockIdx.x * 8 + w) * 4;
    const float* srcp;
    float* dst;
    __nv_bfloat16* bdst;
    if (base_row < NREF) {
        srcp = refs + (size_t)base_row * D; dst = g_y2 + base_row;
        bdst = g_refs_bf + (size_t)base_row * D;
    } else {
        int r = base_row - NREF;
        if (r >= NQ) return;
        srcp = feat + (size_t)r * D; dst = g_x2 + r;
        bdst = g_feat_bf + (size_t)r * D;
    }
    const float4* s4 = (const float4*)srcp;
    float4 v[4];
    v[0] = s4[l]; v[1] = s4[l + 32]; v[2] = s4[l + 64]; v[3] = s4[l + 96];
    float s[4];
    #pragma unroll
    for (int i = 0; i < 4; ++i) {
        s[i] = v[i].x * v[i].x + v[i].y * v[i].y + v[i].z * v[i].z + v[i].w * v[i].w;
        __nv_bfloat162 p0 = __floats2bfloat162_rn(v[i].x, v[i].y);
        __nv_bfloat162 p1 = __floats2bfloat162_rn(v[i].z, v[i].w);
        uint2 packed;
        packed.x = *(uint32_t*)&p0;
        packed.y = *(uint32_t*)&p1;
        ((uint2*)(bdst + (size_t)i * D))[l] = packed;
    }
    #pragma unroll
    for (int o = 16; o; o >>= 1) {
        #pragma unroll
        for (int i = 0; i < 4; ++i) s[i] += __shfl_xor_sync(0xffffffffu, s[i], o);
    }
    if (l == 0) *(float4*)dst = make_float4(s[0], s[1], s[2], s[3]);
}

// ---------------------------------------------------------------- kernel 2: bf16 mma main
__global__ void __launch_bounds__(256, 1)
knn_main_kernel() {
    extern __shared__ __align__(16) unsigned char smem[];
    const uint32_t sAu  = smem_u32(smem);
    const uint32_t sB0u = sAu + TILEB;
    const uint32_t sB1u = sAu + 2 * TILEB;
    float* sD  = (float*)(smem + 3 * TILEB);
    float* sTK = sD + SDF;                   // [128][KNN] per-query top-10 (sorted asc)

    const int t  = threadIdx.x;
    const int w  = t >> 5, l = t & 31;
    const int wm = w >> 2, wn = w & 3;     // warp grid 2(m) x 4(n)
    const int gr = l >> 2, lc = l & 3;     // C-fragment lane coords
    const int phase = l >> 3, pi = l & 7;  // ldmatrix lane roles

    const int split = blockIdx.x;
    const int qbase = blockIdx.y * 128;
    const int sbase = split * NCH * BN;

    // per-lane ldmatrix base addresses
    uint32_t aoff[4];
    {
        const int prow = (phase & 1) * 8 + pi;
        const int pkof = (phase >> 1) * 16;
        #pragma unroll
        for (int it = 0; it < 4; ++it)
            aoff[it] = sAu + (uint32_t)((wm * 64 + it * 16 + prow) * ROWB + pkof);
    }
    uint32_t boff[2];
    {
        const int bn  = (phase >> 1) * 8 + pi;
        const int bkof = (phase & 1) * 16;
        #pragma unroll
        for (int g = 0; g < 2; ++g)
            boff[g] = (uint32_t)((wn * 32 + g * 16 + bn) * ROWB + bkof);
    }

    // prologue: A tile + chunk0 B tile; init top-k table
    load_tile_bf(sAu, g_feat_bf, qbase, qbase + 128);
    load_tile_bf(sB0u, g_refs_bf, sbase, NREF);
    CPA_COMMIT();
    #pragma unroll
    for (int i = t; i < 128 * KNN; i += 256) sTK[i] = BIGF;

    for (int ch = 0; ch < NCH; ++ch) {
        const int cbase = sbase + ch * BN;
        const uint32_t Bcur = (ch & 1) ? sB1u : sB0u;

        // y2 for this thread's 8 output columns
        float y2r[8];
        #pragma unroll
        for (int j = 0; j < 4; ++j) {
            const int c0 = wn * 32 + j * 8 + 2 * lc;
            const int n0 = cbase + c0;
            y2r[2 * j]     = (n0     < NREF) ? g_y2[n0]     : BIGF;
            y2r[2 * j + 1] = (n0 + 1 < NREF) ? g_y2[n0 + 1] : BIGF;
        }

        CPA_WAIT0();
        __syncthreads();      // B(ch) resident; selection of ch-1 done with sD

        // prefetch next chunk's B (overlaps whole k-loop + epilogue + selection)
        if (ch + 1 < NCH)
            load_tile_bf((ch & 1) ? sB0u : sB1u, g_refs_bf, cbase + BN, NREF);
        CPA_COMMIT();

        float acc[4][4][4];
        #pragma unroll
        for (int i = 0; i < 4; ++i)
            #pragma unroll
            for (int j = 0; j < 4; ++j)
                #pragma unroll
                for (int e = 0; e < 4; ++e) acc[i][j][e] = 0.f;

        #pragma unroll
        for (int ks = 0; ks < 8; ++ks) {
            const uint32_t kb = ks * 32;
            uint32_t af[4][4], bf4[2][4];
            #pragma unroll
            for (int it = 0; it < 4; ++it) LDSM4(af[it], aoff[it] + kb);
            #pragma unroll
            for (int g = 0; g < 2; ++g)    LDSM4(bf4[g], Bcur + boff[g] + kb);
            #pragma unroll
            for (int it = 0; it < 4; ++it)
                #pragma unroll
                for (int g = 0; g < 2; ++g)
                    #pragma unroll
                    for (int h = 0; h < 2; ++h)
                        mma_bf16(acc[it][2 * g + h], af[it],
                                 bf4[g][2 * h], bf4[g][2 * h + 1]);
        }

        // epilogue: d^2' = y^2 - 2*dot -> sD
        #pragma unroll
        for (int i = 0; i < 4; ++i) {
            const int r0 = wm * 64 + i * 16 + gr;
            #pragma unroll
            for (int j = 0; j < 4; ++j) {
                const int c0 = wn * 32 + j * 8 + 2 * lc;
                sD[r0 * SDS + c0]           = fmaf(-2.f, acc[i][j][0], y2r[2 * j]);
                sD[r0 * SDS + c0 + 1]       = fmaf(-2.f, acc[i][j][1], y2r[2 * j + 1]);
                sD[(r0 + 8) * SDS + c0]     = fmaf(-2.f, acc[i][j][2], y2r[2 * j]);
                sD[(r0 + 8) * SDS + c0 + 1] = fmaf(-2.f, acc[i][j][3], y2r[2 * j + 1]);
            }
        }
        __syncthreads();

        // warp-ballot selection: warp w owns queries [w*16, w*16+16)
        {
            const int qw = w * 16;
            #pragma unroll 2
            for (int qi = 0; qi < 16; ++qi) {
                const int q = qw + qi;
                float* tkq = sTK + q * KNN;
                float thr = tkq[KNN - 1];
                const float* rowp = sD + q * SDS + l;
                #pragma unroll
                for (int r = 0; r < 4; ++r) {
                    const float v = rowp[r * 32];
                    unsigned m = __ballot_sync(0xffffffffu, v < thr);
                    if (m) {
                        do {
                            const int src = __ffs(m) - 1;
                            m &= m - 1;
                            const float vv = __shfl_sync(0xffffffffu, v, src);
                            if (l == 0 && vv < tkq[KNN - 1]) {
                                tkq[KNN - 1] = vv;
                                #pragma unroll
                                for (int j = KNN - 1; j > 0; --j) {
                                    float lo = fminf(tkq[j - 1], tkq[j]);
                                    float hi = fmaxf(tkq[j - 1], tkq[j]);
                                    tkq[j - 1] = lo;
                                    tkq[j]     = hi;
                                }
                            }
                        } while (m);
                        __syncwarp();
                        thr = tkq[KNN - 1];
                    }
                }
            }
        }
    }

    __syncthreads();
    // write this split's top-K candidates (values are y^2 - 2*dot)
    if (t < 128) {
        const int qg = qbase + t;
        #pragma unroll
        for (int o = 0; o < KNN; ++o)
            g_cand[(split * KNN + o) * NQ + qg] = sTK[t * KNN + o];
    }
}

// ---------------------------------------------------------------- kernel 3: finalize
__global__ void finalize_kernel(float* __restrict__ out) {
    const int q = blockIdx.x * blockDim.x + threadIdx.x;
    if (q >= NQ) return;
    float tk[KNN];
    #pragma unroll
    for (int j = 0; j < KNN; ++j) tk[j] = BIGF;
    #pragma unroll 4
    for (int i = 0; i < NSPLIT * KNN; ++i)
        topk_insert(tk, g_cand[i * NQ + q]);
    const float x2 = g_x2[q];
    float s = 0.f;
    #pragma unroll
    for (int j = 0; j < KNN; ++j) s += sqrtf(fmaxf(x2 + tk[j], 0.f));
    out[q] = -s * (1.0f / KNN);
}

// ---------------------------------------------------------------- launch
extern "C" void kernel_launch(void* const* d_in, const int* in_sizes, int n_in,
                              void* d_out, int out_size) {
    const float* feat = (const float*)d_in[0];
    const float* refs = (const float*)d_in[1];
    if (n_in >= 2 && in_sizes[0] > in_sizes[1]) {
        feat = (const float*)d_in[1];
        refs = (const float*)d_in[0];
    }

    cudaFuncSetAttribute(knn_main_kernel,
                         cudaFuncAttributeMaxDynamicSharedMemorySize, SMEM_BYTES);

    norms_kernel<<<(NREF + NQ) / 32, 256>>>(feat, refs);

    dim3 grid(NSPLIT, NQ / 128);
    knn_main_kernel<<<grid, 256, SMEM_BYTES>>>();

    finalize_kernel<<<2, 256>>>((float*)d_out);
}

// round 7
// speedup vs baseline: 2.8499x; 2.8499x over previous
#include <cuda_runtime.h>
#include <cuda_bf16.h>
#include <cstdint>

#define D      128
#define NQ     512
#define NREF   100000
#define KNN    10
#define NSPLIT 36
#define NCH    22            // 36*22*128 = 101376 >= 100000
#define BN     128
#define NCAND  (NSPLIT * KNN)   // 360 candidates per query
#define ROWB   272           // smem tile row stride in bytes (136 bf16)
#define TILEB  (128 * ROWB)  // 34816 B per bf16 tile
#define SDS    132           // dist buffer row stride (floats, 16B-aligned rows)
#define SDF    (128 * SDS)
#define SMEM_BYTES (3 * TILEB + SDF * 4)   // 172032 B

#define BIGF 3.0e37f

// ---------------------------------------------------------------- scratch
__device__ float g_x2[NQ];
__device__ float g_y2[NREF];
__device__ float g_cand[NQ * NCAND];          // [q][360] for coalesced finalize
__device__ __nv_bfloat16 g_feat_bf[NQ * D];
__device__ __nv_bfloat16 g_refs_bf[NREF * D];

// ---------------------------------------------------------------- helpers
__device__ __forceinline__ uint32_t smem_u32(const void* p) {
    uint32_t a;
    asm("{ .reg .u64 t; cvta.to.shared.u64 t, %1; cvt.u32.u64 %0, t; }" : "=r"(a) : "l"(p));
    return a;
}
__device__ __forceinline__ void cpa16(uint32_t dst, const void* src, int bytes) {
    asm volatile("cp.async.cg.shared.global [%0], [%1], 16, %2;"
                 :: "r"(dst), "l"(src), "r"(bytes) : "memory");
}
#define CPA_COMMIT() asm volatile("cp.async.commit_group;" ::: "memory")
#define CPA_WAIT0()  asm volatile("cp.async.wait_group 0;" ::: "memory")

#define LDSM4(r, a)                                                            \
    asm volatile("ldmatrix.sync.aligned.m8n8.x4.shared.b16 {%0,%1,%2,%3}, [%4];" \
                 : "=r"((r)[0]), "=r"((r)[1]), "=r"((r)[2]), "=r"((r)[3])      \
                 : "r"(a))

__device__ __forceinline__ void mma_bf16(float* c, const uint32_t* a,
                                         uint32_t b0, uint32_t b1) {
    asm volatile("mma.sync.aligned.m16n8k16.row.col.f32.bf16.bf16.f32 "
                 "{%0,%1,%2,%3}, {%4,%5,%6,%7}, {%8,%9}, {%0,%1,%2,%3};"
                 : "+f"(c[0]), "+f"(c[1]), "+f"(c[2]), "+f"(c[3])
                 : "r"(a[0]), "r"(a[1]), "r"(a[2]), "r"(a[3]), "r"(b0), "r"(b1));
}

__device__ __forceinline__ void topk_insert(float (&tk)[KNN], float v) {
    if (v < tk[KNN - 1]) {
        tk[KNN - 1] = v;
        #pragma unroll
        for (int j = KNN - 1; j > 0; --j) {
            float lo = fminf(tk[j - 1], tk[j]);
            float hi = fmaxf(tk[j - 1], tk[j]);
            tk[j - 1] = lo;
            tk[j]     = hi;
        }
    }
}

// Load 128x128 bf16 tile into smem [row][k], row stride ROWB bytes. 512 threads.
__device__ __forceinline__ void load_tile_bf(uint32_t dst, const __nv_bfloat16* __restrict__ src,
                                             int gbase, int glimit) {
    const int t = threadIdx.x;
    const int c = t & 15;           // 16B chunk along k
    const int rb = t >> 4;          // row base (0..31)
    #pragma unroll
    for (int i = 0; i < 4; ++i) {
        const int row = rb + i * 32;
        const int gr = gbase + row;
        const int ok = (gr < glimit) ? 16 : 0;
        const int gc = (gr < glimit) ? gr : (glimit - 1);
        const __nv_bfloat16* s = src + (size_t)gc * D + c * 8;
        cpa16(dst + (uint32_t)(row * ROWB + c * 16), s, ok);
    }
}

// ---------------------------------------------------------------- kernel 1: norms + bf16 convert
__global__ void __launch_bounds__(256)
norms_kernel(const float* __restrict__ feat, const float* __restrict__ refs) {
    const int w = threadIdx.x >> 5, l = threadIdx.x & 31;
    const int base_row = (blockIdx.x * 8 + w) * 4;
    const float* srcp;
    float* dst;
    __nv_bfloat16* bdst;
    if (base_row < NREF) {
        srcp = refs + (size_t)base_row * D; dst = g_y2 + base_row;
        bdst = g_refs_bf + (size_t)base_row * D;
    } else {
        int r = base_row - NREF;
        if (r >= NQ) return;
        srcp = feat + (size_t)r * D; dst = g_x2 + r;
        bdst = g_feat_bf + (size_t)r * D;
    }
    const float4* s4 = (const float4*)srcp;
    float4 v[4];
    v[0] = s4[l]; v[1] = s4[l + 32]; v[2] = s4[l + 64]; v[3] = s4[l + 96];
    float s[4];
    #pragma unroll
    for (int i = 0; i < 4; ++i) {
        s[i] = v[i].x * v[i].x + v[i].y * v[i].y + v[i].z * v[i].z + v[i].w * v[i].w;
        __nv_bfloat162 p0 = __floats2bfloat162_rn(v[i].x, v[i].y);
        __nv_bfloat162 p1 = __floats2bfloat162_rn(v[i].z, v[i].w);
        uint2 packed;
        packed.x = *(uint32_t*)&p0;
        packed.y = *(uint32_t*)&p1;
        ((uint2*)(bdst + (size_t)i * D))[l] = packed;
    }
    #pragma unroll
    for (int o = 16; o; o >>= 1) {
        #pragma unroll
        for (int i = 0; i < 4; ++i) s[i] += __shfl_xor_sync(0xffffffffu, s[i], o);
    }
    if (l == 0) *(float4*)dst = make_float4(s[0], s[1], s[2], s[3]);
}

// ---------------------------------------------------------------- kernel 2: bf16 mma main (512 thr)
__global__ void __launch_bounds__(512, 1)
knn_main_kernel() {
    extern __shared__ __align__(16) unsigned char smem[];
    const uint32_t sAu  = smem_u32(smem);
    const uint32_t sB0u = sAu + TILEB;
    const uint32_t sB1u = sAu + 2 * TILEB;
    float* sD = (float*)(smem + 3 * TILEB);

    const int t  = threadIdx.x;
    const int w  = t >> 5, l = t & 31;
    const int wm = w >> 2, wn = w & 3;     // warp grid 4(m) x 4(n), tile 32x32
    const int gr = l >> 2, lc = l & 3;     // C-fragment lane coords
    const int phase = l >> 3, pi = l & 7;  // ldmatrix lane roles

    const int split = blockIdx.x;
    const int qbase = blockIdx.y * 128;
    const int sbase = split * NCH * BN;

    // ldmatrix base addresses
    uint32_t aoff[2];
    {
        const int prow = (phase & 1) * 8 + pi;
        const int pkof = (phase >> 1) * 16;
        #pragma unroll
        for (int it = 0; it < 2; ++it)
            aoff[it] = sAu + (uint32_t)((wm * 32 + it * 16 + prow) * ROWB + pkof);
    }
    uint32_t boff[2];
    {
        const int bn  = (phase >> 1) * 8 + pi;
        const int bkof = (phase & 1) * 16;
        #pragma unroll
        for (int g = 0; g < 2; ++g)
            boff[g] = (uint32_t)((wn * 32 + g * 16 + bn) * ROWB + bkof);
    }

    // prologue
    load_tile_bf(sAu, g_feat_bf, qbase, qbase + 128);
    load_tile_bf(sB0u, g_refs_bf, sbase, NREF);
    CPA_COMMIT();

    float tk[KNN];
    #pragma unroll
    for (int j = 0; j < KNN; ++j) tk[j] = BIGF;

    for (int ch = 0; ch < NCH; ++ch) {
        const int cbase = sbase + ch * BN;
        const uint32_t Bcur = (ch & 1) ? sB1u : sB0u;

        // y2 for this thread's 8 output columns
        float y2r[8];
        #pragma unroll
        for (int j = 0; j < 4; ++j) {
            const int c0 = wn * 32 + j * 8 + 2 * lc;
            const int n0 = cbase + c0;
            y2r[2 * j]     = (n0     < NREF) ? g_y2[n0]     : BIGF;
            y2r[2 * j + 1] = (n0 + 1 < NREF) ? g_y2[n0 + 1] : BIGF;
        }

        CPA_WAIT0();
        __syncthreads();      // B(ch) resident; selection of ch-1 done with sD

        if (ch + 1 < NCH)
            load_tile_bf((ch & 1) ? sB0u : sB1u, g_refs_bf, cbase + BN, NREF);
        CPA_COMMIT();

        float acc[2][4][4];
        #pragma unroll
        for (int i = 0; i < 2; ++i)
            #pragma unroll
            for (int j = 0; j < 4; ++j)
                #pragma unroll
                for (int e = 0; e < 4; ++e) acc[i][j][e] = 0.f;

        #pragma unroll
        for (int ks = 0; ks < 8; ++ks) {
            const uint32_t kb = ks * 32;
            uint32_t af[2][4], bf4[2][4];
            #pragma unroll
            for (int it = 0; it < 2; ++it) LDSM4(af[it], aoff[it] + kb);
            #pragma unroll
            for (int g = 0; g < 2; ++g)    LDSM4(bf4[g], Bcur + boff[g] + kb);
            #pragma unroll
            for (int it = 0; it < 2; ++it)
                #pragma unroll
                for (int g = 0; g < 2; ++g)
                    #pragma unroll
                    for (int h = 0; h < 2; ++h)
                        mma_bf16(acc[it][2 * g + h], af[it],
                                 bf4[g][2 * h], bf4[g][2 * h + 1]);
        }

        // epilogue: d^2' = y^2 - 2*dot -> sD
        #pragma unroll
        for (int i = 0; i < 2; ++i) {
            const int r0 = wm * 32 + i * 16 + gr;
            #pragma unroll
            for (int j = 0; j < 4; ++j) {
                const int c0 = wn * 32 + j * 8 + 2 * lc;
                sD[r0 * SDS + c0]           = fmaf(-2.f, acc[i][j][0], y2r[2 * j]);
                sD[r0 * SDS + c0 + 1]       = fmaf(-2.f, acc[i][j][1], y2r[2 * j + 1]);
                sD[(r0 + 8) * SDS + c0]     = fmaf(-2.f, acc[i][j][2], y2r[2 * j]);
                sD[(r0 + 8) * SDS + c0 + 1] = fmaf(-2.f, acc[i][j][3], y2r[2 * j + 1]);
            }
        }
        __syncthreads();

        // selection: 4 threads per query, 32 columns each, float4 + min-filter
        {
            const int q = t & 127, s = t >> 7;
            const float4* rowp = (const float4*)(sD + q * SDS + s * 32);
            #pragma unroll
            for (int c = 0; c < 8; ++c) {
                const float4 v = rowp[c];
                const float m = fminf(fminf(v.x, v.y), fminf(v.z, v.w));
                if (m < tk[KNN - 1]) {
                    topk_insert(tk, v.x);
                    topk_insert(tk, v.y);
                    topk_insert(tk, v.z);
                    topk_insert(tk, v.w);
                }
            }
        }
    }

    // merge 4 selectors' sorted lists per query (staged in sD, stride-11 rows + sentinel)
    __syncthreads();
    {
        const int q = t & 127, s = t >> 7;
        #pragma unroll
        for (int j = 0; j < KNN; ++j) sD[(s * 11 + j) * 128 + q] = tk[j];
        sD[(s * 11 + KNN) * 128 + q] = BIGF;   // sentinel
    }
    __syncthreads();
    if (t < 128) {
        int i0 = 0, i1 = 0, i2 = 0, i3 = 0;
        float* dst = g_cand + (size_t)(qbase + t) * NCAND + split * KNN;
        #pragma unroll
        for (int o = 0; o < KNN; ++o) {
            const float h0 = sD[(i0)      * 128 + t];
            const float h1 = sD[(11 + i1) * 128 + t];
            const float h2 = sD[(22 + i2) * 128 + t];
            const float h3 = sD[(33 + i3) * 128 + t];
            const float m = fminf(fminf(h0, h1), fminf(h2, h3));
            dst[o] = m;
            if (m == h0)      ++i0;
            else if (m == h1) ++i1;
            else if (m == h2) ++i2;
            else              ++i3;
        }
    }
}

// ---------------------------------------------------------------- kernel 3: finalize (warp/query)
__global__ void __launch_bounds__(256)
finalize_kernel(float* __restrict__ out) {
    const int w = threadIdx.x >> 5, l = threadIdx.x & 31;
    const int q = blockIdx.x * 8 + w;
    if (q >= NQ) return;
    const float* cp = g_cand + (size_t)q * NCAND;
    const float x2 = g_x2[q];

    float tk[KNN];
    #pragma unroll
    for (int j = 0; j < KNN; ++j) tk[j] = BIGF;
    #pragma unroll
    for (int j = 0; j < 12; ++j) {
        const int i = l + j * 32;
        if (i < NCAND) {
            const float d2 = fmaxf(x2 + cp[i], 0.f);   // clamp -> bits monotone
            topk_insert(tk, d2);
        }
    }
    // 10-round warp merge via uint min-reduce
    float sum = 0.f;
    #pragma unroll
    for (int o = 0; o < KNN; ++o) {
        const unsigned hb = __float_as_uint(tk[0]);
        const unsigned mb = __reduce_min_sync(0xffffffffu, hb);
        sum += sqrtf(__uint_as_float(mb));
        const unsigned msk = __ballot_sync(0xffffffffu, hb == mb);
        if (l == __ffs(msk) - 1) {
            #pragma unroll
            for (int j = 0; j < KNN - 1; ++j) tk[j] = tk[j + 1];
            tk[KNN - 1] = BIGF;
        }
    }
    if (l == 0) out[q] = -sum * (1.0f / KNN);
}

// ---------------------------------------------------------------- launch
extern "C" void kernel_launch(void* const* d_in, const int* in_sizes, int n_in,
                              void* d_out, int out_size) {
    const float* feat = (const float*)d_in[0];
    const float* refs = (const float*)d_in[1];
    if (n_in >= 2 && in_sizes[0] > in_sizes[1]) {
        feat = (const float*)d_in[1];
        refs = (const float*)d_in[0];
    }

    cudaFuncSetAttribute(knn_main_kernel,
                         cudaFuncAttributeMaxDynamicSharedMemorySize, SMEM_BYTES);

    norms_kernel<<<(NREF + NQ) / 32, 256>>>(feat, refs);

    dim3 grid(NSPLIT, NQ / 128);
    knn_main_kernel<<<grid, 512, SMEM_BYTES>>>();

    finalize_kernel<<<NQ / 8, 256>>>((float*)d_out);
}

// round 8
// speedup vs baseline: 2.9604x; 1.0388x over previous
#include <cuda_runtime.h>
#include <cuda_bf16.h>
#include <cstdint>

#define D      128
#define NQ     512
#define NREF   100000
#define KNN    10
#define NSPLIT 36
#define NCH    22            // 36*22*128 = 101376 >= 100000
#define BN     128
#define NCAND  (NSPLIT * KNN)   // 360 candidates per query
#define ROWB   272           // smem tile row stride in bytes (136 bf16)
#define TILEB  (128 * ROWB)  // 34816 B per bf16 tile
#define SDS    132           // dist buffer row stride (floats; 33q%32=q -> conflict-free)
#define SDBUF  (128 * SDS * 4)   // 67584 B per dist buffer
// layout: B0 | B1 | sD0 | sD1   (A tile overlays sD0 during prologue only)
#define SMEM_BYTES (2 * TILEB + 2 * SDBUF)   // 204800 B

#define BIGF 3.0e37f

// ---------------------------------------------------------------- scratch
__device__ float g_x2[NQ];
__device__ float g_y2[NREF];
__device__ float g_cand[NQ * NCAND];          // [q][360] for coalesced finalize
__device__ __nv_bfloat16 g_feat_bf[NQ * D];
__device__ __nv_bfloat16 g_refs_bf[NREF * D];

// ---------------------------------------------------------------- helpers
__device__ __forceinline__ uint32_t smem_u32(const void* p) {
    uint32_t a;
    asm("{ .reg .u64 t; cvta.to.shared.u64 t, %1; cvt.u32.u64 %0, t; }" : "=r"(a) : "l"(p));
    return a;
}
__device__ __forceinline__ void cpa16(uint32_t dst, const void* src, int bytes) {
    asm volatile("cp.async.cg.shared.global [%0], [%1], 16, %2;"
                 :: "r"(dst), "l"(src), "r"(bytes) : "memory");
}
#define CPA_COMMIT() asm volatile("cp.async.commit_group;" ::: "memory")
#define CPA_WAIT0()  asm volatile("cp.async.wait_group 0;" ::: "memory")
#define CPA_WAIT1()  asm volatile("cp.async.wait_group 1;" ::: "memory")

#define LDSM4(r, a)                                                            \
    asm volatile("ldmatrix.sync.aligned.m8n8.x4.shared.b16 {%0,%1,%2,%3}, [%4];" \
                 : "=r"((r)[0]), "=r"((r)[1]), "=r"((r)[2]), "=r"((r)[3])      \
                 : "r"(a))

__device__ __forceinline__ void mma_bf16(float* c, const uint32_t* a,
                                         uint32_t b0, uint32_t b1) {
    asm volatile("mma.sync.aligned.m16n8k16.row.col.f32.bf16.bf16.f32 "
                 "{%0,%1,%2,%3}, {%4,%5,%6,%7}, {%8,%9}, {%0,%1,%2,%3};"
                 : "+f"(c[0]), "+f"(c[1]), "+f"(c[2]), "+f"(c[3])
                 : "r"(a[0]), "r"(a[1]), "r"(a[2]), "r"(a[3]), "r"(b0), "r"(b1));
}

__device__ __forceinline__ void topk_insert(float (&tk)[KNN], float v) {
    if (v < tk[KNN - 1]) {
        tk[KNN - 1] = v;
        #pragma unroll
        for (int j = KNN - 1; j > 0; --j) {
            float lo = fminf(tk[j - 1], tk[j]);
            float hi = fmaxf(tk[j - 1], tk[j]);
            tk[j - 1] = lo;
            tk[j]     = hi;
        }
    }
}

// Load 128x128 bf16 tile into smem [row][k], row stride ROWB bytes. 512 threads.
__device__ __forceinline__ void load_tile_bf(uint32_t dst, const __nv_bfloat16* __restrict__ src,
                                             int gbase, int glimit) {
    const int t = threadIdx.x;
    const int c = t & 15;           // 16B chunk along k
    const int rb = t >> 4;          // row base (0..31)
    #pragma unroll
    for (int i = 0; i < 4; ++i) {
        const int row = rb + i * 32;
        const int gr = gbase + row;
        const int ok = (gr < glimit) ? 16 : 0;
        const int gc = (gr < glimit) ? gr : (glimit - 1);
        const __nv_bfloat16* s = src + (size_t)gc * D + c * 8;
        cpa16(dst + (uint32_t)(row * ROWB + c * 16), s, ok);
    }
}

// ---------------------------------------------------------------- kernel 1: norms + bf16 convert
__global__ void __launch_bounds__(256)
norms_kernel(const float* __restrict__ feat, const float* __restrict__ refs) {
    const int w = threadIdx.x >> 5, l = threadIdx.x & 31;
    const int base_row = (blockIdx.x * 8 + w) * 4;
    const float* srcp;
    float* dst;
    __nv_bfloat16* bdst;
    if (base_row < NREF) {
        srcp = refs + (size_t)base_row * D; dst = g_y2 + base_row;
        bdst = g_refs_bf + (size_t)base_row * D;
    } else {
        int r = base_row - NREF;
        if (r >= NQ) return;
        srcp = feat + (size_t)r * D; dst = g_x2 + r;
        bdst = g_feat_bf + (size_t)r * D;
    }
    const float4* s4 = (const float4*)srcp;
    float4 v[4];
    v[0] = s4[l]; v[1] = s4[l + 32]; v[2] = s4[l + 64]; v[3] = s4[l + 96];
    float s[4];
    #pragma unroll
    for (int i = 0; i < 4; ++i) {
        s[i] = v[i].x * v[i].x + v[i].y * v[i].y + v[i].z * v[i].z + v[i].w * v[i].w;
        __nv_bfloat162 p0 = __floats2bfloat162_rn(v[i].x, v[i].y);
        __nv_bfloat162 p1 = __floats2bfloat162_rn(v[i].z, v[i].w);
        uint2 packed;
        packed.x = *(uint32_t*)&p0;
        packed.y = *(uint32_t*)&p1;
        ((uint2*)(bdst + (size_t)i * D))[l] = packed;
    }
    #pragma unroll
    for (int o = 16; o; o >>= 1) {
        #pragma unroll
        for (int i = 0; i < 4; ++i) s[i] += __shfl_xor_sync(0xffffffffu, s[i], o);
    }
    if (l == 0) *(float4*)dst = make_float4(s[0], s[1], s[2], s[3]);
}

// ---------------------------------------------------------------- kernel 2: bf16 mma main (512 thr)
__global__ void __launch_bounds__(512, 1)
knn_main_kernel() {
    extern __shared__ __align__(16) unsigned char smem[];
    const uint32_t sB0u = smem_u32(smem);
    const uint32_t sB1u = sB0u + TILEB;
    const uint32_t sD0u = sB0u + 2 * TILEB;          // also A staging in prologue
    float* sD0 = (float*)(smem + 2 * TILEB);
    float* sD1 = (float*)(smem + 2 * TILEB + SDBUF);

    const int t  = threadIdx.x;
    const int w  = t >> 5, l = t & 31;
    const int wm = w >> 1, wn = w & 1;     // warp grid 8(m) x 2(n), tile 16x64
    const int gr = l >> 2, lc = l & 3;     // C-fragment lane coords
    const int phase = l >> 3, pi = l & 7;  // ldmatrix lane roles

    const int split = blockIdx.x;
    const int qbase = blockIdx.y * 128;
    const int sbase = split * NCH * BN;

    // ldmatrix addresses
    const int prow = (phase & 1) * 8 + pi;
    const int pkof = (phase >> 1) * 16;
    const uint32_t aaddr = sD0u + (uint32_t)((wm * 16 + prow) * ROWB + pkof);
    uint32_t boff[4];
    {
        const int bn  = (phase >> 1) * 8 + pi;
        const int bkof = (phase & 1) * 16;
        #pragma unroll
        for (int g = 0; g < 4; ++g)
            boff[g] = (uint32_t)((wn * 64 + g * 16 + bn) * ROWB + bkof);
    }

    // prologue: A -> sD0 region (one group), B0 (second group)
    load_tile_bf(sD0u, g_feat_bf, qbase, qbase + 128);
    CPA_COMMIT();
    load_tile_bf(sB0u, g_refs_bf, sbase, NREF);
    CPA_COMMIT();
    CPA_WAIT1();            // A resident (B0 may still be in flight)
    __syncthreads();

    // hoist ALL A fragments (K=128) into registers; A smem then dead
    uint32_t afr[8][4];
    #pragma unroll
    for (int ks = 0; ks < 8; ++ks) LDSM4(afr[ks], aaddr + ks * 32);
    __syncthreads();        // all A reads done before epilogue(ch0) overwrites sD0

    float tk[KNN];
    #pragma unroll
    for (int j = 0; j < KNN; ++j) tk[j] = BIGF;

    for (int ch = 0; ch < NCH; ++ch) {
        const int cbase = sbase + ch * BN;
        const uint32_t Bcur = (ch & 1) ? sB1u : sB0u;
        float* sDw = (ch & 1) ? sD1 : sD0;
        float* sDr = (ch & 1) ? sD0 : sD1;

        CPA_WAIT0();          // B(ch) resident
        __syncthreads();

        if (ch + 1 < NCH)
            load_tile_bf((ch & 1) ? sB0u : sB1u, g_refs_bf, cbase + BN, NREF);
        CPA_COMMIT();

        float acc[8][4];
        #pragma unroll
        for (int j = 0; j < 8; ++j)
            #pragma unroll
            for (int e = 0; e < 4; ++e) acc[j][e] = 0.f;

        #pragma unroll
        for (int ks = 0; ks < 8; ++ks) {
            const uint32_t kb = ks * 32;
            uint32_t bf4[4][4];
            #pragma unroll
            for (int g = 0; g < 4; ++g) LDSM4(bf4[g], Bcur + boff[g] + kb);
            #pragma unroll
            for (int g = 0; g < 4; ++g)
                #pragma unroll
                for (int h = 0; h < 2; ++h)
                    mma_bf16(acc[2 * g + h], afr[ks],
                             bf4[g][2 * h], bf4[g][2 * h + 1]);
        }

        // selection of PREVIOUS chunk (independent of acc -> overlaps MMA drain)
        if (ch > 0) {
            const int q = t & 127, s = t >> 7;
            const float4* rowp = (const float4*)(sDr + q * SDS + s * 32);
            #pragma unroll
            for (int c = 0; c < 8; ++c) {
                const float4 v = rowp[c];
                const float m = fminf(fminf(v.x, v.y), fminf(v.z, v.w));
                if (m < tk[KNN - 1]) {
                    topk_insert(tk, v.x);
                    topk_insert(tk, v.y);
                    topk_insert(tk, v.z);
                    topk_insert(tk, v.w);
                }
            }
        }

        // epilogue: d^2' = y^2 - 2*dot -> sDw (float2 stores)
        {
            const int r0 = wm * 16 + gr;
            #pragma unroll
            for (int j = 0; j < 8; ++j) {
                const int c0 = wn * 64 + j * 8 + 2 * lc;
                const int n0 = cbase + c0;
                float ya, yb;
                if (n0 + 1 < NREF) {
                    const float2 yy = *(const float2*)(g_y2 + n0);
                    ya = yy.x; yb = yy.y;
                } else {
                    ya = (n0 < NREF) ? g_y2[n0] : BIGF;
                    yb = BIGF;
                }
                float2 lo, hi;
                lo.x = fmaf(-2.f, acc[j][0], ya);
                lo.y = fmaf(-2.f, acc[j][1], yb);
                hi.x = fmaf(-2.f, acc[j][2], ya);
                hi.y = fmaf(-2.f, acc[j][3], yb);
                *(float2*)(sDw + r0 * SDS + c0)       = lo;
                *(float2*)(sDw + (r0 + 8) * SDS + c0) = hi;
            }
        }
        __syncthreads();
    }

    // tail: select last chunk
    {
        const int q = t & 127, s = t >> 7;
        float* sDr = ((NCH - 1) & 1) ? sD1 : sD0;
        const float4* rowp = (const float4*)(sDr + q * SDS + s * 32);
        #pragma unroll
        for (int c = 0; c < 8; ++c) {
            const float4 v = rowp[c];
            const float m = fminf(fminf(v.x, v.y), fminf(v.z, v.w));
            if (m < tk[KNN - 1]) {
                topk_insert(tk, v.x);
                topk_insert(tk, v.y);
                topk_insert(tk, v.z);
                topk_insert(tk, v.w);
            }
        }
    }

    // merge 4 selectors' sorted lists per query (staged into sD0 region)
    __syncthreads();
    {
        const int q = t & 127, s = t >> 7;
        #pragma unroll
        for (int j = 0; j < KNN; ++j) sD0[(s * 11 + j) * 128 + q] = tk[j];
        sD0[(s * 11 + KNN) * 128 + q] = BIGF;   // sentinel
    }
    __syncthreads();
    if (t < 128) {
        int i0 = 0, i1 = 0, i2 = 0, i3 = 0;
        float* dst = g_cand + (size_t)(qbase + t) * NCAND + split * KNN;
        #pragma unroll
        for (int o = 0; o < KNN; ++o) {
            const float h0 = sD0[(i0)      * 128 + t];
            const float h1 = sD0[(11 + i1) * 128 + t];
            const float h2 = sD0[(22 + i2) * 128 + t];
            const float h3 = sD0[(33 + i3) * 128 + t];
            const float m = fminf(fminf(h0, h1), fminf(h2, h3));
            dst[o] = m;
            if (m == h0)      ++i0;
            else if (m == h1) ++i1;
            else if (m == h2) ++i2;
            else              ++i3;
        }
    }
}

// ---------------------------------------------------------------- kernel 3: finalize (warp/query)
__global__ void __launch_bounds__(256)
finalize_kernel(float* __restrict__ out) {
    const int w = threadIdx.x >> 5, l = threadIdx.x & 31;
    const int q = blockIdx.x * 8 + w;
    if (q >= NQ) return;
    const float* cp = g_cand + (size_t)q * NCAND;
    const float x2 = g_x2[q];

    float tk[KNN];
    #pragma unroll
    for (int j = 0; j < KNN; ++j) tk[j] = BIGF;
    #pragma unroll
    for (int j = 0; j < 12; ++j) {
        const int i = l + j * 32;
        if (i < NCAND) {
            const float d2 = fmaxf(x2 + cp[i], 0.f);   // clamp -> bits monotone
            topk_insert(tk, d2);
        }
    }
    // 10-round warp merge via uint min-reduce
    float sum = 0.f;
    #pragma unroll
    for (int o = 0; o < KNN; ++o) {
        const unsigned hb = __float_as_uint(tk[0]);
        const unsigned mb = __reduce_min_sync(0xffffffffu, hb);
        sum += sqrtf(__uint_as_float(mb));
        const unsigned msk = __ballot_sync(0xffffffffu, hb == mb);
        if (l == __ffs(msk) - 1) {
            #pragma unroll
            for (int j = 0; j < KNN - 1; ++j) tk[j] = tk[j + 1];
            tk[KNN - 1] = BIGF;
        }
    }
    if (l == 0) out[q] = -sum * (1.0f / KNN);
}

// ---------------------------------------------------------------- launch
extern "C" void kernel_launch(void* const* d_in, const int* in_sizes, int n_in,
                              void* d_out, int out_size) {
    const float* feat = (const float*)d_in[0];
    const float* refs = (const float*)d_in[1];
    if (n_in >= 2 && in_sizes[0] > in_sizes[1]) {
        feat = (const float*)d_in[1];
        refs = (const float*)d_in[0];
    }

    cudaFuncSetAttribute(knn_main_kernel,
                         cudaFuncAttributeMaxDynamicSharedMemorySize, SMEM_BYTES);

    norms_kernel<<<(NREF + NQ) / 32, 256>>>(feat, refs);

    dim3 grid(NSPLIT, NQ / 128);
    knn_main_kernel<<<grid, 512, SMEM_BYTES>>>();

    finalize_kernel<<<NQ / 8, 256>>>((float*)d_out);
}